// round 10
// baseline (speedup 1.0000x reference)
#include <cuda_runtime.h>

#define BB   32
#define NN   2048
#define KK   16
#define FIN  32
#define FOUT 64
#define NPTS (BB * NN)          // 65536
#define PAD  4
#define NS   (NN + 2 * PAD)     // 2056
#define TW   24                 // tau0 window: +-TW Morton neighbors
#define NW   64                 // mask words per query (2048/32)
#define MROW 65                 // padded mask row stride (bank-conflict-free)
#define KNN_THREADS 256
#define KNN_SMEM (NS * 16 + KNN_THREADS * MROW * 4)   // 99456 bytes

// Scratch (allocation-free rule: __device__ globals)
__device__ float4 g_sorted[BB * NS];    // per batch: Morton-sorted (x,y,z, origIdx-bits) + sentinels
__device__ float  g_a[NPTS * FOUT];     // x @ (W1 - W2) + b_edge
__device__ float  g_c[NPTS * FOUT];     // x @ W2
__device__ float  g_s[NPTS * FOUT];     // relu(x @ W_nn + b_nn)
__device__ int    g_idx[NPTS * KK];     // global neighbor indices

// ---------------------------------------------------------------------------
__device__ __forceinline__ unsigned spread3(unsigned x) {
    x &= 0x3FF;
    x = (x | (x << 16)) & 0x030000FF;
    x = (x | (x << 8))  & 0x0300F00F;
    x = (x | (x << 4))  & 0x030C30C3;
    x = (x | (x << 2))  & 0x09249249;
    return x;
}

// ---------------------------------------------------------------------------
// Kernel 0: per-batch Morton sort (7 bits/dim). Bitonic on packed uint32 keys.
// ---------------------------------------------------------------------------
__global__ __launch_bounds__(1024) void sort_kernel(const float* __restrict__ pos) {
    __shared__ float4   spp[NN];
    __shared__ unsigned key[NN];
    __shared__ float    s_red[6][32];
    __shared__ float    s_bounds[6];

    const int b    = blockIdx.x;
    const int tid  = threadIdx.x;
    const int lane = tid & 31;
    const int wid  = tid >> 5;

    for (int i = tid; i < NN; i += 1024) {
        const float* p = pos + (size_t)(b * NN + i) * 3;
        spp[i] = make_float4(p[0], p[1], p[2], __int_as_float(i));
    }
    __syncthreads();

    float mn[3] = { 3e38f, 3e38f, 3e38f }, mx[3] = { -3e38f, -3e38f, -3e38f };
    for (int i = tid; i < NN; i += 1024) {
        float4 q = spp[i];
        mn[0] = fminf(mn[0], q.x); mx[0] = fmaxf(mx[0], q.x);
        mn[1] = fminf(mn[1], q.y); mx[1] = fmaxf(mx[1], q.y);
        mn[2] = fminf(mn[2], q.z); mx[2] = fmaxf(mx[2], q.z);
    }
#pragma unroll
    for (int o = 16; o; o >>= 1) {
#pragma unroll
        for (int d = 0; d < 3; d++) {
            mn[d] = fminf(mn[d], __shfl_xor_sync(0xFFFFFFFFu, mn[d], o));
            mx[d] = fmaxf(mx[d], __shfl_xor_sync(0xFFFFFFFFu, mx[d], o));
        }
    }
    if (lane == 0) {
#pragma unroll
        for (int d = 0; d < 3; d++) { s_red[d][wid] = mn[d]; s_red[3 + d][wid] = mx[d]; }
    }
    __syncthreads();
    if (tid < 32) {
        float v0 = s_red[0][tid], v1 = s_red[1][tid], v2 = s_red[2][tid];
        float v3 = s_red[3][tid], v4 = s_red[4][tid], v5 = s_red[5][tid];
#pragma unroll
        for (int o = 16; o; o >>= 1) {
            v0 = fminf(v0, __shfl_xor_sync(0xFFFFFFFFu, v0, o));
            v1 = fminf(v1, __shfl_xor_sync(0xFFFFFFFFu, v1, o));
            v2 = fminf(v2, __shfl_xor_sync(0xFFFFFFFFu, v2, o));
            v3 = fmaxf(v3, __shfl_xor_sync(0xFFFFFFFFu, v3, o));
            v4 = fmaxf(v4, __shfl_xor_sync(0xFFFFFFFFu, v4, o));
            v5 = fmaxf(v5, __shfl_xor_sync(0xFFFFFFFFu, v5, o));
        }
        if (tid == 0) {
            s_bounds[0] = v0; s_bounds[1] = v1; s_bounds[2] = v2;
            s_bounds[3] = 127.0f / fmaxf(v3 - v0, 1e-12f);
            s_bounds[4] = 127.0f / fmaxf(v4 - v1, 1e-12f);
            s_bounds[5] = 127.0f / fmaxf(v5 - v2, 1e-12f);
        }
    }
    __syncthreads();

    const float mnx = s_bounds[0], mny = s_bounds[1], mnz = s_bounds[2];
    const float sx = s_bounds[3], sy = s_bounds[4], sz = s_bounds[5];
    for (int i = tid; i < NN; i += 1024) {
        float4 q = spp[i];
        unsigned ux = (unsigned)min(max((int)((q.x - mnx) * sx), 0), 127);
        unsigned uy = (unsigned)min(max((int)((q.y - mny) * sy), 0), 127);
        unsigned uz = (unsigned)min(max((int)((q.z - mnz) * sz), 0), 127);
        unsigned code = spread3(ux) | (spread3(uy) << 1) | (spread3(uz) << 2);
        key[i] = (code << 11) | (unsigned)i;
    }

    for (int k = 2; k <= NN; k <<= 1) {
        for (int j = k >> 1; j > 0; j >>= 1) {
            __syncthreads();
            int l = ((tid & ~(j - 1)) << 1) | (tid & (j - 1));
            int p = l | j;
            unsigned A = key[l], Bv = key[p];
            bool asc = (l & k) == 0;
            if ((A > Bv) == asc) { key[l] = Bv; key[p] = A; }
        }
    }
    __syncthreads();

    float4* gs = g_sorted + (size_t)b * NS;
    for (int i = tid; i < NN; i += 1024) gs[PAD + i] = spp[key[i] & 0x7FF];
    if (tid < PAD) {
        gs[tid]            = make_float4(-1.0e30f, -1.0e30f, -1.0e30f, __int_as_float(0));
        gs[PAD + NN + tid] = make_float4( 1.0e30f,  1.0e30f,  1.0e30f, __int_as_float(0));
    }
}

// ---------------------------------------------------------------------------
__device__ __forceinline__ void ins16(float dk[KK], float v) {
#pragma unroll
    for (int k = 0; k < KK; k++) {
        float lo = fminf(dk[k], v);
        v = fmaxf(dk[k], v);
        dk[k] = lo;
    }
}

// ---------------------------------------------------------------------------
// Kernel 1: exact kNN, branchless bitmask main loop (identical to R8).
// Launched 5x this round as an attribution experiment: idempotent, so extra
// launches are correctness-neutral; the total-time delta measures knn itself.
// ---------------------------------------------------------------------------
__global__ __launch_bounds__(KNN_THREADS) void knn_kernel() {
    extern __shared__ unsigned char dynsmem[];
    float4*   sp  = reinterpret_cast<float4*>(dynsmem);             // NS float4
    unsigned* msk = reinterpret_cast<unsigned*>(dynsmem + NS * 16); // THREADS*MROW

    const int b    = blockIdx.x >> 3;
    const int part = blockIdx.x & 7;
    const int tid  = threadIdx.x;

    const float4* gs = g_sorted + (size_t)b * NS;
    for (int i = tid; i < NS; i += KNN_THREADS) sp[i] = gs[i];
    __syncthreads();

    const int rank = (part << 8) + tid;
    const int ic   = PAD + rank;
    const float4 me = sp[ic];

    // ---- A: t0 from +-TW Morton window (two chains, exact union 16th) ----
    float dkL[KK], dkR[KK];
#pragma unroll
    for (int k = 0; k < KK; k++) { dkL[k] = 3.0e38f; dkR[k] = 3.0e38f; }
#pragma unroll 2
    for (int s = 1; s <= TW; s++) {
        float4 ql = sp[max(ic - s, 0)];
        float4 qr = sp[min(ic + s, NS - 1)];
        float dxl = me.x - ql.x, dyl = me.y - ql.y, dzl = me.z - ql.z;
        float dxr = me.x - qr.x, dyr = me.y - qr.y, dzr = me.z - qr.z;
        float d2l = fmaf(dxl, dxl, fmaf(dyl, dyl, dzl * dzl));
        float d2r = fmaf(dxr, dxr, fmaf(dyr, dyr, dzr * dzr));
        ins16(dkL, d2l);
        ins16(dkR, d2r);
    }
    float t0 = 0.f;
#pragma unroll
    for (int i = 0; i < KK; i++)
        t0 = fmaxf(t0, fminf(dkL[i], dkR[KK - 1 - i]));

    // ---- B: branchless bitmask build, 8-wide batches ----
    const int mrow = tid * MROW;
#pragma unroll 1
    for (int w = 0; w < NW; w++) {
        const int jb = PAD + (w << 5);
        unsigned bits = 0u;
#pragma unroll 1
        for (int g8 = 0; g8 < 4; g8++) {
            const int jb8 = jb + (g8 << 3);
            const int sh  = g8 << 3;
#pragma unroll
            for (int u = 0; u < 8; u++) {
                float4 q = sp[jb8 + u];
                float dx = me.x - q.x, dy = me.y - q.y, dz = me.z - q.z;
                float d2 = fmaf(dx, dx, fmaf(dy, dy, dz * dz));
                bits |= (d2 <= t0) ? (1u << (sh + u)) : 0u;
            }
        }
        msk[mrow + w] = bits;
    }
    // clear self bit
    msk[mrow + (rank >> 5)] &= ~(1u << (rank & 31));

    // ---- C1: exact tau over set bits ----
    float sk[KK];
#pragma unroll
    for (int k = 0; k < KK; k++) sk[k] = 3.0e38f;
    for (int w = 0; w < NW; w++) {
        unsigned bits = msk[mrow + w];
        const int jb = PAD + (w << 5);
        while (bits) {
            int u = __ffs(bits) - 1;
            bits &= bits - 1;
            float4 q = sp[jb + u];
            float dx = me.x - q.x, dy = me.y - q.y, dz = me.z - q.z;
            float d2 = fmaf(dx, dx, fmaf(dy, dy, dz * dz));
            ins16(sk, d2);
        }
    }
    const float tau = sk[KK - 1];

    // ---- C2: emit indices with d2 <= tau ----
    const int base = b * NN;
    int* orow = g_idx + (size_t)(base + __float_as_int(me.w)) * KK;
    int k = 0;
    int first = base;
    for (int w = 0; w < NW; w++) {
        unsigned bits = msk[mrow + w];
        const int jb = PAD + (w << 5);
        while (bits) {
            int u = __ffs(bits) - 1;
            bits &= bits - 1;
            float4 q = sp[jb + u];
            float dx = me.x - q.x, dy = me.y - q.y, dz = me.z - q.z;
            float d2 = fmaf(dx, dx, fmaf(dy, dy, dz * dz));
            if (d2 <= tau && k < KK) {
                int g = base + __float_as_int(q.w);
                if (k == 0) first = g;
                orow[k++] = g;
            }
        }
    }
    for (; k < KK; k++) orow[k] = first;   // unreachable safety fill
}

// ---------------------------------------------------------------------------
// Kernel 2: per-node transforms. a = x@(W1-W2)+b_e, c = x@W2, s = relu(x@Wn+bn)
// ---------------------------------------------------------------------------
__global__ __launch_bounds__(128) void transform_kernel(
    const float* __restrict__ x,
    const float* __restrict__ We,
    const float* __restrict__ be,
    const float* __restrict__ Wn,
    const float* __restrict__ bn)
{
    __shared__ float s_wd[FIN * FOUT];
    __shared__ float s_w2[FIN * FOUT];
    __shared__ float s_wn[FIN * FOUT];
    __shared__ float s_be[FOUT];
    __shared__ float s_bn[FOUT];

    const int tid = threadIdx.x;
    for (int t = tid; t < FIN * FOUT; t += 128) {
        float w2 = We[FIN * FOUT + t];
        s_w2[t] = w2;
        s_wd[t] = We[t] - w2;
        s_wn[t] = Wn[t];
    }
    if (tid < FOUT) { s_be[tid] = be[tid]; s_bn[tid] = bn[tid]; }
    __syncthreads();

    const int node = blockIdx.x * 128 + tid;

    float xr[FIN];
#pragma unroll
    for (int r = 0; r < FIN; r += 4) {
        float4 v = *reinterpret_cast<const float4*>(x + (size_t)node * FIN + r);
        xr[r] = v.x; xr[r + 1] = v.y; xr[r + 2] = v.z; xr[r + 3] = v.w;
    }

    for (int f0 = 0; f0 < FOUT; f0 += 4) {
        float a0 = s_be[f0], a1 = s_be[f0 + 1], a2 = s_be[f0 + 2], a3 = s_be[f0 + 3];
        float c0 = 0.f, c1 = 0.f, c2 = 0.f, c3 = 0.f;
        float k0 = s_bn[f0], k1 = s_bn[f0 + 1], k2 = s_bn[f0 + 2], k3 = s_bn[f0 + 3];
#pragma unroll
        for (int r = 0; r < FIN; r++) {
            float xv = xr[r];
            float4 wd = *reinterpret_cast<const float4*>(&s_wd[r * FOUT + f0]);
            float4 w2 = *reinterpret_cast<const float4*>(&s_w2[r * FOUT + f0]);
            float4 wn = *reinterpret_cast<const float4*>(&s_wn[r * FOUT + f0]);
            a0 = fmaf(xv, wd.x, a0); a1 = fmaf(xv, wd.y, a1);
            a2 = fmaf(xv, wd.z, a2); a3 = fmaf(xv, wd.w, a3);
            c0 = fmaf(xv, w2.x, c0); c1 = fmaf(xv, w2.y, c1);
            c2 = fmaf(xv, w2.z, c2); c3 = fmaf(xv, w2.w, c3);
            k0 = fmaf(xv, wn.x, k0); k1 = fmaf(xv, wn.y, k1);
            k2 = fmaf(xv, wn.z, k2); k3 = fmaf(xv, wn.w, k3);
        }
        size_t o = (size_t)node * FOUT + f0;
        *reinterpret_cast<float4*>(&g_a[o]) = make_float4(a0, a1, a2, a3);
        *reinterpret_cast<float4*>(&g_c[o]) = make_float4(c0, c1, c2, c3);
        *reinterpret_cast<float4*>(&g_s[o]) = make_float4(fmaxf(k0, 0.f), fmaxf(k1, 0.f),
                                                          fmaxf(k2, 0.f), fmaxf(k3, 0.f));
    }
}

// ---------------------------------------------------------------------------
// Kernel 3: aggregation, float4 per thread (4 features).
// ---------------------------------------------------------------------------
__global__ __launch_bounds__(256) void aggregate_kernel(float* __restrict__ out) {
    const int gid = blockIdx.x * 256 + threadIdx.x;
    const int i  = gid >> 4;
    const int f4 = (gid & 15) << 2;

    const int4* r4 = reinterpret_cast<const int4*>(g_idx + (size_t)i * KK);
    int4 j0 = r4[0], j1 = r4[1], j2 = r4[2], j3 = r4[3];
    int jj[KK] = { j0.x, j0.y, j0.z, j0.w, j1.x, j1.y, j1.z, j1.w,
                   j2.x, j2.y, j2.z, j2.w, j3.x, j3.y, j3.z, j3.w };

    float4 m = make_float4(-3.0e38f, -3.0e38f, -3.0e38f, -3.0e38f);
#pragma unroll
    for (int k = 0; k < KK; k++) {
        float4 v = *reinterpret_cast<const float4*>(&g_c[(size_t)jj[k] * FOUT + f4]);
        m.x = fmaxf(m.x, v.x); m.y = fmaxf(m.y, v.y);
        m.z = fmaxf(m.z, v.z); m.w = fmaxf(m.w, v.w);
    }

    const size_t o = (size_t)i * FOUT + f4;
    float4 a = *reinterpret_cast<const float4*>(&g_a[o]);
    float4 s = *reinterpret_cast<const float4*>(&g_s[o]);
    float4 r;
    r.x = fmaxf(m.x + a.x, 0.f) + s.x;
    r.y = fmaxf(m.y + a.y, 0.f) + s.y;
    r.z = fmaxf(m.z + a.z, 0.f) + s.z;
    r.w = fmaxf(m.w + a.w, 0.f) + s.w;
    *reinterpret_cast<float4*>(&out[o]) = r;
}

// ---------------------------------------------------------------------------
// ATTRIBUTION EXPERIMENT: knn launched 5x (idempotent). Total-time delta vs
// R8/R9 (~380us) measures knn's true per-launch cost through the noise:
//   knn small (~60-85us) -> total ~600-650 ;  knn big (~330us) -> total ~1700.
// Also raises odds ncu -s 5 -c 1 lands on knn_kernel for a direct profile.
// ---------------------------------------------------------------------------
extern "C" void kernel_launch(void* const* d_in, const int* in_sizes, int n_in,
                              void* d_out, int out_size) {
    const float* x   = (const float*)d_in[0];
    const float* pos = (const float*)d_in[1];
    const float* We  = (const float*)d_in[2];
    const float* be  = (const float*)d_in[3];
    const float* Wn  = (const float*)d_in[4];
    const float* bn  = (const float*)d_in[5];
    float* out = (float*)d_out;

    cudaFuncSetAttribute(knn_kernel, cudaFuncAttributeMaxDynamicSharedMemorySize, KNN_SMEM);

    sort_kernel<<<BB, 1024>>>(pos);
    knn_kernel<<<BB * 8, KNN_THREADS, KNN_SMEM>>>();
    knn_kernel<<<BB * 8, KNN_THREADS, KNN_SMEM>>>();
    knn_kernel<<<BB * 8, KNN_THREADS, KNN_SMEM>>>();
    knn_kernel<<<BB * 8, KNN_THREADS, KNN_SMEM>>>();
    knn_kernel<<<BB * 8, KNN_THREADS, KNN_SMEM>>>();
    transform_kernel<<<NPTS / 128, 128>>>(x, We, be, Wn, bn);
    aggregate_kernel<<<(NPTS * FOUT / 4) / 256, 256>>>(out);
}

// round 11
// speedup vs baseline: 5.2281x; 5.2281x over previous
#include <cuda_runtime.h>

#define BB   32
#define NN   2048
#define KK   16
#define FIN  32
#define FOUT 64
#define NPTS (BB * NN)          // 65536
#define PAD  4
#define NS   (NN + 2 * PAD)     // 2056
#define TW   24                 // tau0 window: +-TW Morton neighbors
#define NSEG 4                  // segments (threads) per query
#define QPB  128                // queries per block
#define KNN_THREADS (QPB * NSEG)            // 512
#define SEGW 16                 // mask words per segment (512/32)
#define MSTR 17                 // padded per-thread stride (words / floats)

// SMEM layout (bytes)
#define OFF_SP    0
#define OFF_MASK  (NS * 16)                              // 32896
#define OFF_VALS  (OFF_MASK + KNN_THREADS * MSTR * 4)    // 67712
#define OFF_TAU   (OFF_VALS + KNN_THREADS * MSTR * 4)    // 102528
#define OFF_CNT   (OFF_TAU + QPB * 4)                    // 103040
#define KNN_SMEM  (OFF_CNT + QPB * 4)                    // 103552

// Scratch (allocation-free rule: __device__ globals)
__device__ float4 g_sorted[BB * NS];    // per batch: Morton-sorted (x,y,z, origIdx-bits) + sentinels
__device__ float  g_a[NPTS * FOUT];     // x @ (W1 - W2) + b_edge
__device__ float  g_c[NPTS * FOUT];     // x @ W2
__device__ float  g_s[NPTS * FOUT];     // relu(x @ W_nn + b_nn)
__device__ int    g_idx[NPTS * KK];     // global neighbor indices

// ---------------------------------------------------------------------------
__device__ __forceinline__ unsigned spread3(unsigned x) {
    x &= 0x3FF;
    x = (x | (x << 16)) & 0x030000FF;
    x = (x | (x << 8))  & 0x0300F00F;
    x = (x | (x << 4))  & 0x030C30C3;
    x = (x | (x << 2))  & 0x09249249;
    return x;
}

// ---------------------------------------------------------------------------
// Kernel 0: per-batch Morton sort (7 bits/dim). Bitonic on packed uint32 keys.
// ---------------------------------------------------------------------------
__global__ __launch_bounds__(1024) void sort_kernel(const float* __restrict__ pos) {
    __shared__ float4   spp[NN];
    __shared__ unsigned key[NN];
    __shared__ float    s_red[6][32];
    __shared__ float    s_bounds[6];

    const int b    = blockIdx.x;
    const int tid  = threadIdx.x;
    const int lane = tid & 31;
    const int wid  = tid >> 5;

    for (int i = tid; i < NN; i += 1024) {
        const float* p = pos + (size_t)(b * NN + i) * 3;
        spp[i] = make_float4(p[0], p[1], p[2], __int_as_float(i));
    }
    __syncthreads();

    float mn[3] = { 3e38f, 3e38f, 3e38f }, mx[3] = { -3e38f, -3e38f, -3e38f };
    for (int i = tid; i < NN; i += 1024) {
        float4 q = spp[i];
        mn[0] = fminf(mn[0], q.x); mx[0] = fmaxf(mx[0], q.x);
        mn[1] = fminf(mn[1], q.y); mx[1] = fmaxf(mx[1], q.y);
        mn[2] = fminf(mn[2], q.z); mx[2] = fmaxf(mx[2], q.z);
    }
#pragma unroll
    for (int o = 16; o; o >>= 1) {
#pragma unroll
        for (int d = 0; d < 3; d++) {
            mn[d] = fminf(mn[d], __shfl_xor_sync(0xFFFFFFFFu, mn[d], o));
            mx[d] = fmaxf(mx[d], __shfl_xor_sync(0xFFFFFFFFu, mx[d], o));
        }
    }
    if (lane == 0) {
#pragma unroll
        for (int d = 0; d < 3; d++) { s_red[d][wid] = mn[d]; s_red[3 + d][wid] = mx[d]; }
    }
    __syncthreads();
    if (tid < 32) {
        float v0 = s_red[0][tid], v1 = s_red[1][tid], v2 = s_red[2][tid];
        float v3 = s_red[3][tid], v4 = s_red[4][tid], v5 = s_red[5][tid];
#pragma unroll
        for (int o = 16; o; o >>= 1) {
            v0 = fminf(v0, __shfl_xor_sync(0xFFFFFFFFu, v0, o));
            v1 = fminf(v1, __shfl_xor_sync(0xFFFFFFFFu, v1, o));
            v2 = fminf(v2, __shfl_xor_sync(0xFFFFFFFFu, v2, o));
            v3 = fmaxf(v3, __shfl_xor_sync(0xFFFFFFFFu, v3, o));
            v4 = fmaxf(v4, __shfl_xor_sync(0xFFFFFFFFu, v4, o));
            v5 = fmaxf(v5, __shfl_xor_sync(0xFFFFFFFFu, v5, o));
        }
        if (tid == 0) {
            s_bounds[0] = v0; s_bounds[1] = v1; s_bounds[2] = v2;
            s_bounds[3] = 127.0f / fmaxf(v3 - v0, 1e-12f);
            s_bounds[4] = 127.0f / fmaxf(v4 - v1, 1e-12f);
            s_bounds[5] = 127.0f / fmaxf(v5 - v2, 1e-12f);
        }
    }
    __syncthreads();

    const float mnx = s_bounds[0], mny = s_bounds[1], mnz = s_bounds[2];
    const float sx = s_bounds[3], sy = s_bounds[4], sz = s_bounds[5];
    for (int i = tid; i < NN; i += 1024) {
        float4 q = spp[i];
        unsigned ux = (unsigned)min(max((int)((q.x - mnx) * sx), 0), 127);
        unsigned uy = (unsigned)min(max((int)((q.y - mny) * sy), 0), 127);
        unsigned uz = (unsigned)min(max((int)((q.z - mnz) * sz), 0), 127);
        unsigned code = spread3(ux) | (spread3(uy) << 1) | (spread3(uz) << 2);
        key[i] = (code << 11) | (unsigned)i;
    }

    for (int k = 2; k <= NN; k <<= 1) {
        for (int j = k >> 1; j > 0; j >>= 1) {
            __syncthreads();
            int l = ((tid & ~(j - 1)) << 1) | (tid & (j - 1));
            int p = l | j;
            unsigned A = key[l], Bv = key[p];
            bool asc = (l & k) == 0;
            if ((A > Bv) == asc) { key[l] = Bv; key[p] = A; }
        }
    }
    __syncthreads();

    float4* gs = g_sorted + (size_t)b * NS;
    for (int i = tid; i < NN; i += 1024) gs[PAD + i] = spp[key[i] & 0x7FF];
    if (tid < PAD) {
        gs[tid]            = make_float4(-1.0e30f, -1.0e30f, -1.0e30f, __int_as_float(0));
        gs[PAD + NN + tid] = make_float4( 1.0e30f,  1.0e30f,  1.0e30f, __int_as_float(0));
    }
}

// ---------------------------------------------------------------------------
__device__ __forceinline__ void ins16(float dk[KK], float v) {
#pragma unroll
    for (int k = 0; k < KK; k++) {
        float lo = fminf(dk[k], v);
        v = fmaxf(dk[k], v);
        dk[k] = lo;
    }
}

// ---------------------------------------------------------------------------
// Kernel 1: exact kNN, 4 threads per query (segment-parallel).
//  A) every thread: t0 = exact 16th-smallest d2 in +-TW Morton window.
//  B) build branchless bitmask over OWN 512-candidate segment (SMEM words).
//  C) walk own bits -> per-segment sorted top-16 values -> SMEM.
//  D) leader (seg 0) merges 4x16 -> exact tau; zeroes emit counter.
//  E) every thread re-walks own bits, emits d2<=tau via SMEM atomic slots.
//     (max-pool is order-invariant, so emission order is irrelevant.)
// 4x more warps than thread-per-query => occ ~50% instead of 16%.
// ---------------------------------------------------------------------------
__global__ __launch_bounds__(KNN_THREADS) void knn_kernel() {
    extern __shared__ unsigned char dynsmem[];
    float4*   sp    = reinterpret_cast<float4*>(dynsmem + OFF_SP);
    unsigned* smask = reinterpret_cast<unsigned*>(dynsmem + OFF_MASK);
    float*    svals = reinterpret_cast<float*>(dynsmem + OFF_VALS);
    float*    stau  = reinterpret_cast<float*>(dynsmem + OFF_TAU);
    int*      scnt  = reinterpret_cast<int*>(dynsmem + OFF_CNT);

    const int b    = blockIdx.x >> 4;          // 16 blocks per batch
    const int part = blockIdx.x & 15;
    const int t    = threadIdx.x;
    const int q    = t & (QPB - 1);            // query slot within block
    const int seg  = t >> 7;                   // segment 0..3

    const float4* gs = g_sorted + (size_t)b * NS;
    for (int i = t; i < NS; i += KNN_THREADS) sp[i] = gs[i];
    __syncthreads();

    const int rank = (part << 7) + q;
    const int ic   = PAD + rank;
    const float4 me = sp[ic];

    // ---- A: t0 from +-TW Morton window (redundant across segments) ----
    float dkL[KK], dkR[KK];
#pragma unroll
    for (int k = 0; k < KK; k++) { dkL[k] = 3.0e38f; dkR[k] = 3.0e38f; }
#pragma unroll 2
    for (int s = 1; s <= TW; s++) {
        float4 ql = sp[max(ic - s, 0)];
        float4 qr = sp[min(ic + s, NS - 1)];
        float dxl = me.x - ql.x, dyl = me.y - ql.y, dzl = me.z - ql.z;
        float dxr = me.x - qr.x, dyr = me.y - qr.y, dzr = me.z - qr.z;
        float d2l = fmaf(dxl, dxl, fmaf(dyl, dyl, dzl * dzl));
        float d2r = fmaf(dxr, dxr, fmaf(dyr, dyr, dzr * dzr));
        ins16(dkL, d2l);
        ins16(dkR, d2r);
    }
    float t0 = 0.f;
#pragma unroll
    for (int i = 0; i < KK; i++)
        t0 = fmaxf(t0, fminf(dkL[i], dkR[KK - 1 - i]));

    // ---- B: branchless mask build over own 512-candidate segment ----
    const int mbase = t * MSTR;
    const int segbase = PAD + (seg << 9);
#pragma unroll 1
    for (int w = 0; w < SEGW; w++) {
        const int jb = segbase + (w << 5);
        unsigned bits = 0u;
#pragma unroll 1
        for (int g8 = 0; g8 < 4; g8++) {
            const int jb8 = jb + (g8 << 3);
            const int sh  = g8 << 3;
#pragma unroll
            for (int u = 0; u < 8; u++) {
                float4 p = sp[jb8 + u];
                float dx = me.x - p.x, dy = me.y - p.y, dz = me.z - p.z;
                float d2 = fmaf(dx, dx, fmaf(dy, dy, dz * dz));
                bits |= (d2 <= t0) ? (1u << (sh + u)) : 0u;
            }
        }
        smask[mbase + w] = bits;
    }
    // clear self bit if it lives in this segment
    if ((rank >> 9) == seg)
        smask[mbase + ((rank >> 5) & (SEGW - 1))] &= ~(1u << (rank & 31));

    // ---- C: partial top-16 values over own bits ----
    float dk[KK];
#pragma unroll
    for (int k = 0; k < KK; k++) dk[k] = 3.0e38f;
#pragma unroll 1
    for (int w = 0; w < SEGW; w++) {
        unsigned bits = smask[mbase + w];
        const int jb = segbase + (w << 5);
        while (bits) {
            int u = __ffs(bits) - 1;
            bits &= bits - 1;
            float4 p = sp[jb + u];
            float dx = me.x - p.x, dy = me.y - p.y, dz = me.z - p.z;
            float d2 = fmaf(dx, dx, fmaf(dy, dy, dz * dz));
            ins16(dk, d2);
        }
    }
#pragma unroll
    for (int i = 0; i < KK; i++) svals[mbase + i] = dk[i];
    __syncthreads();

    // ---- D: leader merges 4 partial top-16s -> exact tau ----
    if (seg == 0) {
        float sk[KK];
#pragma unroll
        for (int k = 0; k < KK; k++) sk[k] = 3.0e38f;
#pragma unroll 1
        for (int s = 0; s < NSEG; s++) {
            const int vb = ((s << 7) + q) * MSTR;
#pragma unroll
            for (int i = 0; i < KK; i++) ins16(sk, svals[vb + i]);
        }
        stau[q] = sk[KK - 1];
        scnt[q] = 0;
    }
    __syncthreads();

    // ---- E: emit own bits with d2 <= tau via atomic slot assignment ----
    const float tau = stau[q];
    const int base = b * NN;
    int* orow = g_idx + (size_t)(base + __float_as_int(me.w)) * KK;
#pragma unroll 1
    for (int w = 0; w < SEGW; w++) {
        unsigned bits = smask[mbase + w];
        const int jb = segbase + (w << 5);
        while (bits) {
            int u = __ffs(bits) - 1;
            bits &= bits - 1;
            float4 p = sp[jb + u];
            float dx = me.x - p.x, dy = me.y - p.y, dz = me.z - p.z;
            float d2 = fmaf(dx, dx, fmaf(dy, dy, dz * dz));
            if (d2 <= tau) {
                int pos = atomicAdd(&scnt[q], 1);
                if (pos < KK) orow[pos] = base + __float_as_int(p.w);
            }
        }
    }
    __syncthreads();

    // ---- safety fill (ties/degenerate; normally cnt >= 16) ----
    if (seg == 0) {
        int c = min(scnt[q], KK);
        if (c < KK) {
            int f = (c > 0) ? orow[0] : base;
            for (int k = c; k < KK; k++) orow[k] = f;
        }
    }
}

// ---------------------------------------------------------------------------
// Kernel 2: per-node transforms. a = x@(W1-W2)+b_e, c = x@W2, s = relu(x@Wn+bn)
// ---------------------------------------------------------------------------
__global__ __launch_bounds__(128) void transform_kernel(
    const float* __restrict__ x,
    const float* __restrict__ We,
    const float* __restrict__ be,
    const float* __restrict__ Wn,
    const float* __restrict__ bn)
{
    __shared__ float s_wd[FIN * FOUT];
    __shared__ float s_w2[FIN * FOUT];
    __shared__ float s_wn[FIN * FOUT];
    __shared__ float s_be[FOUT];
    __shared__ float s_bn[FOUT];

    const int tid = threadIdx.x;
    for (int t = tid; t < FIN * FOUT; t += 128) {
        float w2 = We[FIN * FOUT + t];
        s_w2[t] = w2;
        s_wd[t] = We[t] - w2;
        s_wn[t] = Wn[t];
    }
    if (tid < FOUT) { s_be[tid] = be[tid]; s_bn[tid] = bn[tid]; }
    __syncthreads();

    const int node = blockIdx.x * 128 + tid;

    float xr[FIN];
#pragma unroll
    for (int r = 0; r < FIN; r += 4) {
        float4 v = *reinterpret_cast<const float4*>(x + (size_t)node * FIN + r);
        xr[r] = v.x; xr[r + 1] = v.y; xr[r + 2] = v.z; xr[r + 3] = v.w;
    }

    for (int f0 = 0; f0 < FOUT; f0 += 4) {
        float a0 = s_be[f0], a1 = s_be[f0 + 1], a2 = s_be[f0 + 2], a3 = s_be[f0 + 3];
        float c0 = 0.f, c1 = 0.f, c2 = 0.f, c3 = 0.f;
        float k0 = s_bn[f0], k1 = s_bn[f0 + 1], k2 = s_bn[f0 + 2], k3 = s_bn[f0 + 3];
#pragma unroll
        for (int r = 0; r < FIN; r++) {
            float xv = xr[r];
            float4 wd = *reinterpret_cast<const float4*>(&s_wd[r * FOUT + f0]);
            float4 w2 = *reinterpret_cast<const float4*>(&s_w2[r * FOUT + f0]);
            float4 wn = *reinterpret_cast<const float4*>(&s_wn[r * FOUT + f0]);
            a0 = fmaf(xv, wd.x, a0); a1 = fmaf(xv, wd.y, a1);
            a2 = fmaf(xv, wd.z, a2); a3 = fmaf(xv, wd.w, a3);
            c0 = fmaf(xv, w2.x, c0); c1 = fmaf(xv, w2.y, c1);
            c2 = fmaf(xv, w2.z, c2); c3 = fmaf(xv, w2.w, c3);
            k0 = fmaf(xv, wn.x, k0); k1 = fmaf(xv, wn.y, k1);
            k2 = fmaf(xv, wn.z, k2); k3 = fmaf(xv, wn.w, k3);
        }
        size_t o = (size_t)node * FOUT + f0;
        *reinterpret_cast<float4*>(&g_a[o]) = make_float4(a0, a1, a2, a3);
        *reinterpret_cast<float4*>(&g_c[o]) = make_float4(c0, c1, c2, c3);
        *reinterpret_cast<float4*>(&g_s[o]) = make_float4(fmaxf(k0, 0.f), fmaxf(k1, 0.f),
                                                          fmaxf(k2, 0.f), fmaxf(k3, 0.f));
    }
}

// ---------------------------------------------------------------------------
// Kernel 3: aggregation, float4 per thread (4 features).
// ---------------------------------------------------------------------------
__global__ __launch_bounds__(256) void aggregate_kernel(float* __restrict__ out) {
    const int gid = blockIdx.x * 256 + threadIdx.x;
    const int i  = gid >> 4;
    const int f4 = (gid & 15) << 2;

    const int4* r4 = reinterpret_cast<const int4*>(g_idx + (size_t)i * KK);
    int4 j0 = r4[0], j1 = r4[1], j2 = r4[2], j3 = r4[3];
    int jj[KK] = { j0.x, j0.y, j0.z, j0.w, j1.x, j1.y, j1.z, j1.w,
                   j2.x, j2.y, j2.z, j2.w, j3.x, j3.y, j3.z, j3.w };

    float4 m = make_float4(-3.0e38f, -3.0e38f, -3.0e38f, -3.0e38f);
#pragma unroll
    for (int k = 0; k < KK; k++) {
        float4 v = *reinterpret_cast<const float4*>(&g_c[(size_t)jj[k] * FOUT + f4]);
        m.x = fmaxf(m.x, v.x); m.y = fmaxf(m.y, v.y);
        m.z = fmaxf(m.z, v.z); m.w = fmaxf(m.w, v.w);
    }

    const size_t o = (size_t)i * FOUT + f4;
    float4 a = *reinterpret_cast<const float4*>(&g_a[o]);
    float4 s = *reinterpret_cast<const float4*>(&g_s[o]);
    float4 r;
    r.x = fmaxf(m.x + a.x, 0.f) + s.x;
    r.y = fmaxf(m.y + a.y, 0.f) + s.y;
    r.z = fmaxf(m.z + a.z, 0.f) + s.z;
    r.w = fmaxf(m.w + a.w, 0.f) + s.w;
    *reinterpret_cast<float4*>(&out[o]) = r;
}

// ---------------------------------------------------------------------------
extern "C" void kernel_launch(void* const* d_in, const int* in_sizes, int n_in,
                              void* d_out, int out_size) {
    const float* x   = (const float*)d_in[0];
    const float* pos = (const float*)d_in[1];
    const float* We  = (const float*)d_in[2];
    const float* be  = (const float*)d_in[3];
    const float* Wn  = (const float*)d_in[4];
    const float* bn  = (const float*)d_in[5];
    float* out = (float*)d_out;

    cudaFuncSetAttribute(knn_kernel, cudaFuncAttributeMaxDynamicSharedMemorySize, KNN_SMEM);

    sort_kernel<<<BB, 1024>>>(pos);
    knn_kernel<<<BB * 16, KNN_THREADS, KNN_SMEM>>>();
    transform_kernel<<<NPTS / 128, 128>>>(x, We, be, Wn, bn);
    aggregate_kernel<<<(NPTS * FOUT / 4) / 256, 256>>>(out);
}

// round 12
// speedup vs baseline: 5.5915x; 1.0695x over previous
#include <cuda_runtime.h>

#define BB   32
#define NN   2048
#define KK   16
#define FIN  32
#define FOUT 64
#define NPTS (BB * NN)          // 65536
#define PAD  4
#define NS   (NN + 2 * PAD)     // 2056
#define TW   24                 // t0 window: +-TW Morton neighbors
#define NSEG 4                  // segments (threads) per query
#define QPB  128                // queries per block
#define KNN_THREADS (QPB * NSEG)            // 512
#define SEGW 16                 // mask words per segment (512/32)
#define NWORD 64                // words per batch (2048/32)
#define MSTR 17                 // padded per-thread stride (words / floats)

// SMEM layout (bytes)
#define OFF_SP    0
#define OFF_BOX   (NS * 16)                              // 32896: 64 boxes x 2 float4
#define OFF_MASK  (OFF_BOX + NWORD * 32)                 // 34944
#define OFF_VALS  (OFF_MASK + KNN_THREADS * MSTR * 4)    // 69760
#define OFF_TAU0  (OFF_VALS + KNN_THREADS * MSTR * 4)    // 104576
#define OFF_TAU   (OFF_TAU0 + QPB * 4)                   // 105088
#define OFF_CNT   (OFF_TAU + QPB * 4)                    // 105600
#define KNN_SMEM  (OFF_CNT + QPB * 4)                    // 106112

// Scratch (allocation-free rule: __device__ globals)
__device__ float4 g_sorted[BB * NS];    // per batch: Morton-sorted (x,y,z, origIdx-bits) + sentinels
__device__ float  g_a[NPTS * FOUT];     // x @ (W1 - W2) + b_edge
__device__ float  g_c[NPTS * FOUT];     // x @ W2
__device__ float  g_s[NPTS * FOUT];     // relu(x @ W_nn + b_nn)
__device__ int    g_idx[NPTS * KK];     // global neighbor indices

// ---------------------------------------------------------------------------
__device__ __forceinline__ unsigned spread3(unsigned x) {
    x &= 0x3FF;
    x = (x | (x << 16)) & 0x030000FF;
    x = (x | (x << 8))  & 0x0300F00F;
    x = (x | (x << 4))  & 0x030C30C3;
    x = (x | (x << 2))  & 0x09249249;
    return x;
}

// ---------------------------------------------------------------------------
// Kernel 0: per-batch Morton sort (7 bits/dim). Bitonic on packed uint32 keys.
// ---------------------------------------------------------------------------
__global__ __launch_bounds__(1024) void sort_kernel(const float* __restrict__ pos) {
    __shared__ float4   spp[NN];
    __shared__ unsigned key[NN];
    __shared__ float    s_red[6][32];
    __shared__ float    s_bounds[6];

    const int b    = blockIdx.x;
    const int tid  = threadIdx.x;
    const int lane = tid & 31;
    const int wid  = tid >> 5;

    for (int i = tid; i < NN; i += 1024) {
        const float* p = pos + (size_t)(b * NN + i) * 3;
        spp[i] = make_float4(p[0], p[1], p[2], __int_as_float(i));
    }
    __syncthreads();

    float mn[3] = { 3e38f, 3e38f, 3e38f }, mx[3] = { -3e38f, -3e38f, -3e38f };
    for (int i = tid; i < NN; i += 1024) {
        float4 q = spp[i];
        mn[0] = fminf(mn[0], q.x); mx[0] = fmaxf(mx[0], q.x);
        mn[1] = fminf(mn[1], q.y); mx[1] = fmaxf(mx[1], q.y);
        mn[2] = fminf(mn[2], q.z); mx[2] = fmaxf(mx[2], q.z);
    }
#pragma unroll
    for (int o = 16; o; o >>= 1) {
#pragma unroll
        for (int d = 0; d < 3; d++) {
            mn[d] = fminf(mn[d], __shfl_xor_sync(0xFFFFFFFFu, mn[d], o));
            mx[d] = fmaxf(mx[d], __shfl_xor_sync(0xFFFFFFFFu, mx[d], o));
        }
    }
    if (lane == 0) {
#pragma unroll
        for (int d = 0; d < 3; d++) { s_red[d][wid] = mn[d]; s_red[3 + d][wid] = mx[d]; }
    }
    __syncthreads();
    if (tid < 32) {
        float v0 = s_red[0][tid], v1 = s_red[1][tid], v2 = s_red[2][tid];
        float v3 = s_red[3][tid], v4 = s_red[4][tid], v5 = s_red[5][tid];
#pragma unroll
        for (int o = 16; o; o >>= 1) {
            v0 = fminf(v0, __shfl_xor_sync(0xFFFFFFFFu, v0, o));
            v1 = fminf(v1, __shfl_xor_sync(0xFFFFFFFFu, v1, o));
            v2 = fminf(v2, __shfl_xor_sync(0xFFFFFFFFu, v2, o));
            v3 = fmaxf(v3, __shfl_xor_sync(0xFFFFFFFFu, v3, o));
            v4 = fmaxf(v4, __shfl_xor_sync(0xFFFFFFFFu, v4, o));
            v5 = fmaxf(v5, __shfl_xor_sync(0xFFFFFFFFu, v5, o));
        }
        if (tid == 0) {
            s_bounds[0] = v0; s_bounds[1] = v1; s_bounds[2] = v2;
            s_bounds[3] = 127.0f / fmaxf(v3 - v0, 1e-12f);
            s_bounds[4] = 127.0f / fmaxf(v4 - v1, 1e-12f);
            s_bounds[5] = 127.0f / fmaxf(v5 - v2, 1e-12f);
        }
    }
    __syncthreads();

    const float mnx = s_bounds[0], mny = s_bounds[1], mnz = s_bounds[2];
    const float sx = s_bounds[3], sy = s_bounds[4], sz = s_bounds[5];
    for (int i = tid; i < NN; i += 1024) {
        float4 q = spp[i];
        unsigned ux = (unsigned)min(max((int)((q.x - mnx) * sx), 0), 127);
        unsigned uy = (unsigned)min(max((int)((q.y - mny) * sy), 0), 127);
        unsigned uz = (unsigned)min(max((int)((q.z - mnz) * sz), 0), 127);
        unsigned code = spread3(ux) | (spread3(uy) << 1) | (spread3(uz) << 2);
        key[i] = (code << 11) | (unsigned)i;
    }

    for (int k = 2; k <= NN; k <<= 1) {
        for (int j = k >> 1; j > 0; j >>= 1) {
            __syncthreads();
            int l = ((tid & ~(j - 1)) << 1) | (tid & (j - 1));
            int p = l | j;
            unsigned A = key[l], Bv = key[p];
            bool asc = (l & k) == 0;
            if ((A > Bv) == asc) { key[l] = Bv; key[p] = A; }
        }
    }
    __syncthreads();

    float4* gs = g_sorted + (size_t)b * NS;
    for (int i = tid; i < NN; i += 1024) gs[PAD + i] = spp[key[i] & 0x7FF];
    if (tid < PAD) {
        gs[tid]            = make_float4(-1.0e30f, -1.0e30f, -1.0e30f, __int_as_float(0));
        gs[PAD + NN + tid] = make_float4( 1.0e30f,  1.0e30f,  1.0e30f, __int_as_float(0));
    }
}

// ---------------------------------------------------------------------------
__device__ __forceinline__ void ins16(float dk[KK], float v) {
#pragma unroll
    for (int k = 0; k < KK; k++) {
        float lo = fminf(dk[k], v);
        v = fmaxf(dk[k], v);
        dk[k] = lo;
    }
}

// ---------------------------------------------------------------------------
// Kernel 1: exact kNN, 4 threads/query + per-word AABB culling.
//  0) build 64 word-AABBs (32 Morton-adjacent points each) in SMEM.
//  A) seg-0 warps: t0 = exact 16th-smallest d2 in +-TW window -> SMEM.
//  B) per word: AABB lower-bound test (warp-uniform via __any_sync);
//     surviving words get the branchless 32-candidate bitmask build.
//  C) walk own bits -> per-segment top-16 values -> SMEM.
//  D) leader merges 4x16 -> exact tau.
//  E) re-walk own bits, emit d2<=tau via SMEM-atomic slots (order-free).
// ---------------------------------------------------------------------------
__global__ __launch_bounds__(KNN_THREADS) void knn_kernel() {
    extern __shared__ unsigned char dynsmem[];
    float4*   sp    = reinterpret_cast<float4*>(dynsmem + OFF_SP);
    float4*   sbox  = reinterpret_cast<float4*>(dynsmem + OFF_BOX);   // [gw*2]=min, [gw*2+1]=max
    unsigned* smask = reinterpret_cast<unsigned*>(dynsmem + OFF_MASK);
    float*    svals = reinterpret_cast<float*>(dynsmem + OFF_VALS);
    float*    stau0 = reinterpret_cast<float*>(dynsmem + OFF_TAU0);
    float*    stau  = reinterpret_cast<float*>(dynsmem + OFF_TAU);
    int*      scnt  = reinterpret_cast<int*>(dynsmem + OFF_CNT);

    const int b    = blockIdx.x >> 4;          // 16 blocks per batch
    const int part = blockIdx.x & 15;
    const int t    = threadIdx.x;
    const int q    = t & (QPB - 1);            // query slot within block
    const int seg  = t >> 7;                   // segment 0..3

    const float4* gs = g_sorted + (size_t)b * NS;
    for (int i = t; i < NS; i += KNN_THREADS) sp[i] = gs[i];
    __syncthreads();

    // ---- 0: word AABBs (one thread per word; one-time) ----
    if (t < NWORD) {
        const int jb = PAD + (t << 5);
        float4 p0 = sp[jb];
        float mnx = p0.x, mxx = p0.x, mny = p0.y, mxy = p0.y, mnz = p0.z, mxz = p0.z;
#pragma unroll 4
        for (int i = 1; i < 32; i++) {
            float4 p = sp[jb + i];
            mnx = fminf(mnx, p.x); mxx = fmaxf(mxx, p.x);
            mny = fminf(mny, p.y); mxy = fmaxf(mxy, p.y);
            mnz = fminf(mnz, p.z); mxz = fmaxf(mxz, p.z);
        }
        sbox[(t << 1)]     = make_float4(mnx, mny, mnz, 0.f);
        sbox[(t << 1) + 1] = make_float4(mxx, mxy, mxz, 0.f);
    }

    const int rank = (part << 7) + q;
    const int ic   = PAD + rank;
    const float4 me = sp[ic];

    // ---- A: t0 by seg-0 warps only ----
    if (seg == 0) {
        float dkL[KK], dkR[KK];
#pragma unroll
        for (int k = 0; k < KK; k++) { dkL[k] = 3.0e38f; dkR[k] = 3.0e38f; }
#pragma unroll 2
        for (int s = 1; s <= TW; s++) {
            float4 ql = sp[max(ic - s, 0)];
            float4 qr = sp[min(ic + s, NS - 1)];
            float dxl = me.x - ql.x, dyl = me.y - ql.y, dzl = me.z - ql.z;
            float dxr = me.x - qr.x, dyr = me.y - qr.y, dzr = me.z - qr.z;
            float d2l = fmaf(dxl, dxl, fmaf(dyl, dyl, dzl * dzl));
            float d2r = fmaf(dxr, dxr, fmaf(dyr, dyr, dzr * dzr));
            ins16(dkL, d2l);
            ins16(dkR, d2r);
        }
        float t0v = 0.f;
#pragma unroll
        for (int i = 0; i < KK; i++)
            t0v = fmaxf(t0v, fminf(dkL[i], dkR[KK - 1 - i]));
        stau0[q] = t0v;
    }
    __syncthreads();

    const float t0  = stau0[q];
    const float t0b = t0 * 1.0001f;   // box-test slack absorbs fp rounding

    // ---- B: AABB-culled branchless mask build over own segment ----
    const int mbase = t * MSTR;
    const int segbase = PAD + (seg << 9);
#pragma unroll 1
    for (int w = 0; w < SEGW; w++) {
        const int gw = (seg << 4) + w;
        float4 bmn = sbox[(gw << 1)];
        float4 bmx = sbox[(gw << 1) + 1];
        float ex = fmaxf(fmaxf(bmn.x - me.x, me.x - bmx.x), 0.f);
        float ey = fmaxf(fmaxf(bmn.y - me.y, me.y - bmx.y), 0.f);
        float ez = fmaxf(fmaxf(bmn.z - me.z, me.z - bmx.z), 0.f);
        float lb = fmaf(ex, ex, fmaf(ey, ey, ez * ez));

        unsigned bits = 0u;
        if (__any_sync(0xFFFFFFFFu, lb <= t0b)) {   // warp-uniform branch
            const int jb = segbase + (w << 5);
#pragma unroll 1
            for (int g8 = 0; g8 < 4; g8++) {
                const int jb8 = jb + (g8 << 3);
                const int sh  = g8 << 3;
#pragma unroll
                for (int u = 0; u < 8; u++) {
                    float4 p = sp[jb8 + u];
                    float dx = me.x - p.x, dy = me.y - p.y, dz = me.z - p.z;
                    float d2 = fmaf(dx, dx, fmaf(dy, dy, dz * dz));
                    bits |= (d2 <= t0) ? (1u << (sh + u)) : 0u;
                }
            }
        }
        smask[mbase + w] = bits;
    }
    // clear self bit if it lives in this segment
    if ((rank >> 9) == seg)
        smask[mbase + ((rank >> 5) & (SEGW - 1))] &= ~(1u << (rank & 31));

    // ---- C: partial top-16 values over own bits ----
    float dk[KK];
#pragma unroll
    for (int k = 0; k < KK; k++) dk[k] = 3.0e38f;
#pragma unroll 1
    for (int w = 0; w < SEGW; w++) {
        unsigned bits = smask[mbase + w];
        const int jb = segbase + (w << 5);
        while (bits) {
            int u = __ffs(bits) - 1;
            bits &= bits - 1;
            float4 p = sp[jb + u];
            float dx = me.x - p.x, dy = me.y - p.y, dz = me.z - p.z;
            float d2 = fmaf(dx, dx, fmaf(dy, dy, dz * dz));
            ins16(dk, d2);
        }
    }
#pragma unroll
    for (int i = 0; i < KK; i++) svals[mbase + i] = dk[i];
    __syncthreads();

    // ---- D: leader merges 4 partial top-16s -> exact tau ----
    if (seg == 0) {
        float sk[KK];
#pragma unroll
        for (int k = 0; k < KK; k++) sk[k] = 3.0e38f;
#pragma unroll 1
        for (int s = 0; s < NSEG; s++) {
            const int vb = ((s << 7) + q) * MSTR;
#pragma unroll
            for (int i = 0; i < KK; i++) ins16(sk, svals[vb + i]);
        }
        stau[q] = sk[KK - 1];
        scnt[q] = 0;
    }
    __syncthreads();

    // ---- E: emit own bits with d2 <= tau via atomic slot assignment ----
    const float tau = stau[q];
    const int base = b * NN;
    int* orow = g_idx + (size_t)(base + __float_as_int(me.w)) * KK;
#pragma unroll 1
    for (int w = 0; w < SEGW; w++) {
        unsigned bits = smask[mbase + w];
        const int jb = segbase + (w << 5);
        while (bits) {
            int u = __ffs(bits) - 1;
            bits &= bits - 1;
            float4 p = sp[jb + u];
            float dx = me.x - p.x, dy = me.y - p.y, dz = me.z - p.z;
            float d2 = fmaf(dx, dx, fmaf(dy, dy, dz * dz));
            if (d2 <= tau) {
                int pos = atomicAdd(&scnt[q], 1);
                if (pos < KK) orow[pos] = base + __float_as_int(p.w);
            }
        }
    }
    __syncthreads();

    // ---- safety fill (ties/degenerate; normally cnt >= 16) ----
    if (seg == 0) {
        int c = min(scnt[q], KK);
        if (c < KK) {
            int f = (c > 0) ? orow[0] : base;
            for (int k = c; k < KK; k++) orow[k] = f;
        }
    }
}

// ---------------------------------------------------------------------------
// Kernel 2: per-node transforms. a = x@(W1-W2)+b_e, c = x@W2, s = relu(x@Wn+bn)
// ---------------------------------------------------------------------------
__global__ __launch_bounds__(128) void transform_kernel(
    const float* __restrict__ x,
    const float* __restrict__ We,
    const float* __restrict__ be,
    const float* __restrict__ Wn,
    const float* __restrict__ bn)
{
    __shared__ float s_wd[FIN * FOUT];
    __shared__ float s_w2[FIN * FOUT];
    __shared__ float s_wn[FIN * FOUT];
    __shared__ float s_be[FOUT];
    __shared__ float s_bn[FOUT];

    const int tid = threadIdx.x;
    for (int t = tid; t < FIN * FOUT; t += 128) {
        float w2 = We[FIN * FOUT + t];
        s_w2[t] = w2;
        s_wd[t] = We[t] - w2;
        s_wn[t] = Wn[t];
    }
    if (tid < FOUT) { s_be[tid] = be[tid]; s_bn[tid] = bn[tid]; }
    __syncthreads();

    const int node = blockIdx.x * 128 + tid;

    float xr[FIN];
#pragma unroll
    for (int r = 0; r < FIN; r += 4) {
        float4 v = *reinterpret_cast<const float4*>(x + (size_t)node * FIN + r);
        xr[r] = v.x; xr[r + 1] = v.y; xr[r + 2] = v.z; xr[r + 3] = v.w;
    }

    for (int f0 = 0; f0 < FOUT; f0 += 4) {
        float a0 = s_be[f0], a1 = s_be[f0 + 1], a2 = s_be[f0 + 2], a3 = s_be[f0 + 3];
        float c0 = 0.f, c1 = 0.f, c2 = 0.f, c3 = 0.f;
        float k0 = s_bn[f0], k1 = s_bn[f0 + 1], k2 = s_bn[f0 + 2], k3 = s_bn[f0 + 3];
#pragma unroll
        for (int r = 0; r < FIN; r++) {
            float xv = xr[r];
            float4 wd = *reinterpret_cast<const float4*>(&s_wd[r * FOUT + f0]);
            float4 w2 = *reinterpret_cast<const float4*>(&s_w2[r * FOUT + f0]);
            float4 wn = *reinterpret_cast<const float4*>(&s_wn[r * FOUT + f0]);
            a0 = fmaf(xv, wd.x, a0); a1 = fmaf(xv, wd.y, a1);
            a2 = fmaf(xv, wd.z, a2); a3 = fmaf(xv, wd.w, a3);
            c0 = fmaf(xv, w2.x, c0); c1 = fmaf(xv, w2.y, c1);
            c2 = fmaf(xv, w2.z, c2); c3 = fmaf(xv, w2.w, c3);
            k0 = fmaf(xv, wn.x, k0); k1 = fmaf(xv, wn.y, k1);
            k2 = fmaf(xv, wn.z, k2); k3 = fmaf(xv, wn.w, k3);
        }
        size_t o = (size_t)node * FOUT + f0;
        *reinterpret_cast<float4*>(&g_a[o]) = make_float4(a0, a1, a2, a3);
        *reinterpret_cast<float4*>(&g_c[o]) = make_float4(c0, c1, c2, c3);
        *reinterpret_cast<float4*>(&g_s[o]) = make_float4(fmaxf(k0, 0.f), fmaxf(k1, 0.f),
                                                          fmaxf(k2, 0.f), fmaxf(k3, 0.f));
    }
}

// ---------------------------------------------------------------------------
// Kernel 3: aggregation, float4 per thread (4 features).
// ---------------------------------------------------------------------------
__global__ __launch_bounds__(256) void aggregate_kernel(float* __restrict__ out) {
    const int gid = blockIdx.x * 256 + threadIdx.x;
    const int i  = gid >> 4;
    const int f4 = (gid & 15) << 2;

    const int4* r4 = reinterpret_cast<const int4*>(g_idx + (size_t)i * KK);
    int4 j0 = r4[0], j1 = r4[1], j2 = r4[2], j3 = r4[3];
    int jj[KK] = { j0.x, j0.y, j0.z, j0.w, j1.x, j1.y, j1.z, j1.w,
                   j2.x, j2.y, j2.z, j2.w, j3.x, j3.y, j3.z, j3.w };

    float4 m = make_float4(-3.0e38f, -3.0e38f, -3.0e38f, -3.0e38f);
#pragma unroll
    for (int k = 0; k < KK; k++) {
        float4 v = *reinterpret_cast<const float4*>(&g_c[(size_t)jj[k] * FOUT + f4]);
        m.x = fmaxf(m.x, v.x); m.y = fmaxf(m.y, v.y);
        m.z = fmaxf(m.z, v.z); m.w = fmaxf(m.w, v.w);
    }

    const size_t o = (size_t)i * FOUT + f4;
    float4 a = *reinterpret_cast<const float4*>(&g_a[o]);
    float4 s = *reinterpret_cast<const float4*>(&g_s[o]);
    float4 r;
    r.x = fmaxf(m.x + a.x, 0.f) + s.x;
    r.y = fmaxf(m.y + a.y, 0.f) + s.y;
    r.z = fmaxf(m.z + a.z, 0.f) + s.z;
    r.w = fmaxf(m.w + a.w, 0.f) + s.w;
    *reinterpret_cast<float4*>(&out[o]) = r;
}

// ---------------------------------------------------------------------------
extern "C" void kernel_launch(void* const* d_in, const int* in_sizes, int n_in,
                              void* d_out, int out_size) {
    const float* x   = (const float*)d_in[0];
    const float* pos = (const float*)d_in[1];
    const float* We  = (const float*)d_in[2];
    const float* be  = (const float*)d_in[3];
    const float* Wn  = (const float*)d_in[4];
    const float* bn  = (const float*)d_in[5];
    float* out = (float*)d_out;

    cudaFuncSetAttribute(knn_kernel, cudaFuncAttributeMaxDynamicSharedMemorySize, KNN_SMEM);

    sort_kernel<<<BB, 1024>>>(pos);
    knn_kernel<<<BB * 16, KNN_THREADS, KNN_SMEM>>>();
    transform_kernel<<<NPTS / 128, 128>>>(x, We, be, Wn, bn);
    aggregate_kernel<<<(NPTS * FOUT / 4) / 256, 256>>>(out);
}